// round 1
// baseline (speedup 1.0000x reference)
#include <cuda_runtime.h>
#include <math.h>

// Problem constants
// B=32, T=1024, D_IN=80, enc: 80->512->512->256 (ReLU), F=768, 4H=1024, H=256

// ------------------------- device scratch -------------------------
__device__ float d_buf0[32768 * 512];       // enc L0 out
__device__ float d_buf1[32768 * 512];       // enc L1 out
__device__ float d_h[32768 * 256];          // enc L2 out (h)
__device__ float d_d1[32768 * 256];         // delta1
__device__ float d_feat[32768 * 768];       // sorted features [sb][t][f]
__device__ float d_Z[67108864];             // [dir][sb][t][j] precomputed x@Wih^T + b
__device__ float d_Hbuf[2][2][256][32];     // [parity][dir][k][b]
__device__ float d_Hout[2][1024][256][32];  // [dir][t][k][b]
__device__ int d_order[32];
__device__ int d_lens[32];
__device__ unsigned d_ctr;

// ------------------------- order (stable argsort desc) -------------------------
__global__ void compute_order_k(const int* __restrict__ xlen) {
    if (threadIdx.x == 0) {
        unsigned used = 0;
        for (int p = 0; p < 32; ++p) {
            int best = -1, bl = -2147483647;
            for (int j = 0; j < 32; ++j) {
                if (used & (1u << j)) continue;
                int L = xlen[j];
                if (L > bl) { bl = L; best = j; }
            }
            used |= (1u << best);
            d_order[p] = best;
            d_lens[p] = bl;
        }
        d_ctr = 0u;
    }
}

// ------------------------- generic fp32 GEMM + bias + ReLU -------------------------
// C[M][N] = relu(A[M][K] @ W[N][K]^T + bias[N]); M%128==0, N%128==0, K%8==0
__global__ void __launch_bounds__(256) gemm_relu_k(
    const float* __restrict__ A, const float* __restrict__ W,
    const float* __restrict__ bias, float* __restrict__ C,
    int M, int N, int K) {
    __shared__ float As[8][132];
    __shared__ float Ws[8][132];
    const int tid = threadIdx.x;
    const int n0 = blockIdx.x * 128, m0 = blockIdx.y * 128;
    const int lm = tid >> 1, lq = (tid & 1) * 4;
    const float* arow = A + (size_t)(m0 + lm) * K + lq;
    const float* wrow = W + (size_t)(n0 + lm) * K + lq;
    const int tx = tid & 15, ty = tid >> 4;
    float acc[8][8];
#pragma unroll
    for (int i = 0; i < 8; i++)
#pragma unroll
        for (int j = 0; j < 8; j++) acc[i][j] = 0.f;

    for (int k0 = 0; k0 < K; k0 += 8) {
        float4 av = *(const float4*)(arow + k0);
        float4 wv = *(const float4*)(wrow + k0);
        __syncthreads();
        As[lq + 0][lm] = av.x; As[lq + 1][lm] = av.y;
        As[lq + 2][lm] = av.z; As[lq + 3][lm] = av.w;
        Ws[lq + 0][lm] = wv.x; Ws[lq + 1][lm] = wv.y;
        Ws[lq + 2][lm] = wv.z; Ws[lq + 3][lm] = wv.w;
        __syncthreads();
#pragma unroll
        for (int k = 0; k < 8; k++) {
            float a[8], b[8];
            *(float4*)(a) = *(const float4*)&As[k][ty * 8];
            *(float4*)(a + 4) = *(const float4*)&As[k][ty * 8 + 4];
            *(float4*)(b) = *(const float4*)&Ws[k][tx * 8];
            *(float4*)(b + 4) = *(const float4*)&Ws[k][tx * 8 + 4];
#pragma unroll
            for (int i = 0; i < 8; i++)
#pragma unroll
                for (int j = 0; j < 8; j++) acc[i][j] += a[i] * b[j];
        }
    }
    float bs[8];
    *(float4*)bs = *(const float4*)&bias[n0 + tx * 8];
    *(float4*)(bs + 4) = *(const float4*)&bias[n0 + tx * 8 + 4];
#pragma unroll
    for (int i = 0; i < 8; i++) {
        float* crow = C + (size_t)(m0 + ty * 8 + i) * N + n0 + tx * 8;
        float4 v0, v1;
        v0.x = fmaxf(acc[i][0] + bs[0], 0.f);
        v0.y = fmaxf(acc[i][1] + bs[1], 0.f);
        v0.z = fmaxf(acc[i][2] + bs[2], 0.f);
        v0.w = fmaxf(acc[i][3] + bs[3], 0.f);
        v1.x = fmaxf(acc[i][4] + bs[4], 0.f);
        v1.y = fmaxf(acc[i][5] + bs[5], 0.f);
        v1.z = fmaxf(acc[i][6] + bs[6], 0.f);
        v1.w = fmaxf(acc[i][7] + bs[7], 0.f);
        *(float4*)crow = v0;
        *(float4*)(crow + 4) = v1;
    }
}

// ------------------------- deltas (WIN=2, edge replicate) -------------------------
__global__ void deltas_k() {
    int idx = blockIdx.x * 256 + threadIdx.x;  // over 32*1024*64 float4 chunks
    if (idx >= 32 * 1024 * 64) return;
    int c4 = idx & 63, t = (idx >> 6) & 1023, b = idx >> 16;
    const float4* h4 = (const float4*)d_h;
    size_t base = (size_t)b * 65536;  // in float4 units per batch: 1024*64
    int tp1 = min(t + 1, 1023), tm1 = max(t - 1, 0);
    int tp2 = min(t + 2, 1023), tm2 = max(t - 2, 0);
    float4 a = h4[base + (size_t)tp1 * 64 + c4];
    float4 bb = h4[base + (size_t)tm1 * 64 + c4];
    float4 c = h4[base + (size_t)tp2 * 64 + c4];
    float4 d = h4[base + (size_t)tm2 * 64 + c4];
    float4 z;
    z.x = (a.x - bb.x) * 0.5f + (c.x - d.x) * 0.25f;
    z.y = (a.y - bb.y) * 0.5f + (c.y - d.y) * 0.25f;
    z.z = (a.z - bb.z) * 0.5f + (c.z - d.z) * 0.25f;
    z.w = (a.w - bb.w) * 0.5f + (c.w - d.w) * 0.25f;
    ((float4*)d_d1)[base + (size_t)t * 64 + c4] = z;
}

// ------------------------- feat assembly (sorted) -------------------------
__global__ void feat_k() {
    int idx = blockIdx.x * 256 + threadIdx.x;
    if (idx >= 32 * 1024 * 64) return;
    int c4 = idx & 63, t = (idx >> 6) & 1023, sb = idx >> 16;
    int b = d_order[sb];
    const float4* h4 = (const float4*)d_h;
    const float4* d14 = (const float4*)d_d1;
    float4* f4 = (float4*)d_feat;
    size_t base = (size_t)b * 65536;
    size_t srow = base + (size_t)t * 64 + c4;
    float4 hv = h4[srow];
    float4 d1v = d14[srow];
    int tp1 = min(t + 1, 1023), tm1 = max(t - 1, 0);
    int tp2 = min(t + 2, 1023), tm2 = max(t - 2, 0);
    float4 a = d14[base + (size_t)tp1 * 64 + c4];
    float4 bb = d14[base + (size_t)tm1 * 64 + c4];
    float4 c = d14[base + (size_t)tp2 * 64 + c4];
    float4 d = d14[base + (size_t)tm2 * 64 + c4];
    float4 d2v;
    d2v.x = (a.x - bb.x) * 0.5f + (c.x - d.x) * 0.25f;
    d2v.y = (a.y - bb.y) * 0.5f + (c.y - d.y) * 0.25f;
    d2v.z = (a.z - bb.z) * 0.5f + (c.z - d.z) * 0.25f;
    d2v.w = (a.w - bb.w) * 0.5f + (c.w - d.w) * 0.25f;
    size_t obase = ((size_t)sb * 1024 + t) * 192;  // 768/4
    f4[obase + c4] = hv;
    f4[obase + 64 + c4] = d1v;
    f4[obase + 128 + c4] = d2v;
}

// ------------------------- Z = feat(dir-remap) @ Wih^T + (b_ih+b_hh) -------------------------
__global__ void __launch_bounds__(256) zgemm_k(
    const float* __restrict__ Wih_f, const float* __restrict__ Wih_b,
    const float* __restrict__ bihf, const float* __restrict__ bhhf,
    const float* __restrict__ bihb, const float* __restrict__ bhhb) {
    __shared__ float As[8][132];
    __shared__ float Ws[8][132];
    const int tid = threadIdx.x;
    const int dir = blockIdx.z;
    const int n0 = blockIdx.x * 128, m0 = blockIdx.y * 128;
    const int lm = tid >> 1, lq = (tid & 1) * 4;
    const int m = m0 + lm;
    const int sb = m >> 10, t = m & 1023;
    int trow = t;
    if (dir) {
        int L = d_lens[sb];
        trow = L - 1 - t;
        trow = trow < 0 ? 0 : (trow > 1023 ? 1023 : trow);
    }
    const float* arow = d_feat + ((size_t)sb * 1024 + trow) * 768 + lq;
    const float* W = dir ? Wih_b : Wih_f;
    const float* wrow = W + (size_t)(n0 + lm) * 768 + lq;
    const int tx = tid & 15, ty = tid >> 4;
    float acc[8][8];
#pragma unroll
    for (int i = 0; i < 8; i++)
#pragma unroll
        for (int j = 0; j < 8; j++) acc[i][j] = 0.f;

    for (int k0 = 0; k0 < 768; k0 += 8) {
        float4 av = *(const float4*)(arow + k0);
        float4 wv = *(const float4*)(wrow + k0);
        __syncthreads();
        As[lq + 0][lm] = av.x; As[lq + 1][lm] = av.y;
        As[lq + 2][lm] = av.z; As[lq + 3][lm] = av.w;
        Ws[lq + 0][lm] = wv.x; Ws[lq + 1][lm] = wv.y;
        Ws[lq + 2][lm] = wv.z; Ws[lq + 3][lm] = wv.w;
        __syncthreads();
#pragma unroll
        for (int k = 0; k < 8; k++) {
            float a[8], b[8];
            *(float4*)(a) = *(const float4*)&As[k][ty * 8];
            *(float4*)(a + 4) = *(const float4*)&As[k][ty * 8 + 4];
            *(float4*)(b) = *(const float4*)&Ws[k][tx * 8];
            *(float4*)(b + 4) = *(const float4*)&Ws[k][tx * 8 + 4];
#pragma unroll
            for (int i = 0; i < 8; i++)
#pragma unroll
                for (int j = 0; j < 8; j++) acc[i][j] += a[i] * b[j];
        }
    }
    const float* b1p = dir ? bihb : bihf;
    const float* b2p = dir ? bhhb : bhhf;
    float bs[8];
    {
        float4 u0 = *(const float4*)&b1p[n0 + tx * 8];
        float4 u1 = *(const float4*)&b1p[n0 + tx * 8 + 4];
        float4 v0 = *(const float4*)&b2p[n0 + tx * 8];
        float4 v1 = *(const float4*)&b2p[n0 + tx * 8 + 4];
        bs[0] = u0.x + v0.x; bs[1] = u0.y + v0.y; bs[2] = u0.z + v0.z; bs[3] = u0.w + v0.w;
        bs[4] = u1.x + v1.x; bs[5] = u1.y + v1.y; bs[6] = u1.z + v1.z; bs[7] = u1.w + v1.w;
    }
#pragma unroll
    for (int i = 0; i < 8; i++) {
        float* crow = d_Z + ((size_t)dir * 32768 + (m0 + ty * 8 + i)) * 1024 + n0 + tx * 8;
        float4 v0, v1;
        v0.x = acc[i][0] + bs[0]; v0.y = acc[i][1] + bs[1];
        v0.z = acc[i][2] + bs[2]; v0.w = acc[i][3] + bs[3];
        v1.x = acc[i][4] + bs[4]; v1.y = acc[i][5] + bs[5];
        v1.z = acc[i][6] + bs[6]; v1.w = acc[i][7] + bs[7];
        *(float4*)crow = v0;
        *(float4*)(crow + 4) = v1;
    }
}

// ------------------------- persistent bidirectional LSTM recurrence -------------------------
// 128 CTAs: cta>>6 = dir, cta&63 = slice (owns h indices slice*4..slice*4+3 -> 16 gate rows)
__global__ void __launch_bounds__(256, 1) lstm_rec_k(
    const float* __restrict__ Whh_f, const float* __restrict__ Whh_b,
    const float* __restrict__ h0, const float* __restrict__ c0) {
    extern __shared__ float sm[];
    float* sW = sm;                 // [k][r]: k*16+r   (16 KB)
    float* sH = sm + 4096;          // [b][k]: b*260+k  (33.3 KB)
    float* sG = sm + 4096 + 8320;   // [r][b]: r*33+b   (2.1 KB)
    const int tid = threadIdx.x;
    const int cta = blockIdx.x;
    const int dir = cta >> 6;
    const int slice = cta & 63;
    const float* Whh = dir ? Whh_b : Whh_f;

    // stage Whh slice into smem (transposed, k-major)
    for (int i = tid; i < 4096; i += 256) {
        int rr = i >> 8, k = i & 255;
        int j = ((rr >> 2) << 8) + (slice << 2) + (rr & 3);
        sW[k * 16 + rr] = Whh[(size_t)j * 256 + k];
    }

    const int uq = tid >> 5, ub = tid & 31;  // update-thread mapping (tid<128)
    float creg = 0.f;
    if (tid < 128) {
        int kidx = (slice << 2) + uq;
        creg = c0[(dir * 32 + ub) * 256 + kidx];
        d_Hbuf[0][dir][kidx][ub] = h0[(dir * 32 + ub) * 256 + kidx];
    }
    __threadfence();
    __syncthreads();
    if (tid == 0) {
        atomicAdd(&d_ctr, 1u);
        while (*((volatile unsigned*)&d_ctr) < 128u) {}
    }
    __syncthreads();

    const int w = tid >> 5, lane = tid & 31;
    const int r = lane & 15, bh = lane >> 4;
    const int b0 = (w << 2) + bh, b1 = b0 + 2;
    const int jg = ((r >> 2) << 8) + (slice << 2) + (r & 3);
    const float* Z0 = d_Z + (((size_t)(dir * 32 + b0)) << 20) + jg;
    const float* Z1 = d_Z + (((size_t)(dir * 32 + b1)) << 20) + jg;
    unsigned target = 128u;

    for (int t = 0; t < 1024; ++t) {
        float acc0 = __ldg(Z0 + ((size_t)t << 10));
        float acc1 = __ldg(Z1 + ((size_t)t << 10));
        // pull h_{t-1} (all 256 x 32) from L2, transpose to [b][k]
        const float4* gh = (const float4*)&d_Hbuf[t & 1][dir][0][0];
#pragma unroll
        for (int it = 0; it < 8; ++it) {
            int i = tid + it * 256;
            float4 v = __ldcg(gh + i);
            int k = i >> 3, bq = (i & 7) << 2;
            sH[(bq + 0) * 260 + k] = v.x;
            sH[(bq + 1) * 260 + k] = v.y;
            sH[(bq + 2) * 260 + k] = v.z;
            sH[(bq + 3) * 260 + k] = v.w;
        }
        __syncthreads();
        const float* h0p = sH + b0 * 260;
        const float* h1p = sH + b1 * 260;
        float a0 = 0.f, a1 = 0.f, a2 = 0.f, a3 = 0.f;
        float e0 = 0.f, e1 = 0.f, e2 = 0.f, e3 = 0.f;
#pragma unroll 8
        for (int k = 0; k < 256; k += 4) {
            float4 hv0 = *(const float4*)(h0p + k);
            float4 hv1 = *(const float4*)(h1p + k);
            float w0 = sW[(k + 0) * 16 + r];
            float w1 = sW[(k + 1) * 16 + r];
            float w2 = sW[(k + 2) * 16 + r];
            float w3 = sW[(k + 3) * 16 + r];
            a0 += hv0.x * w0; a1 += hv0.y * w1; a2 += hv0.z * w2; a3 += hv0.w * w3;
            e0 += hv1.x * w0; e1 += hv1.y * w1; e2 += hv1.z * w2; e3 += hv1.w * w3;
        }
        acc0 += (a0 + a1) + (a2 + a3);
        acc1 += (e0 + e1) + (e2 + e3);
        sG[r * 33 + b0] = acc0;
        sG[r * 33 + b1] = acc1;
        __syncthreads();
        if (tid < 128) {
            float ig = sG[uq * 33 + ub];
            float fg = sG[(4 + uq) * 33 + ub];
            float gg = sG[(8 + uq) * 33 + ub];
            float og = sG[(12 + uq) * 33 + ub];
            float is = 1.f / (1.f + expf(-ig));
            float fs = 1.f / (1.f + expf(-fg));
            float os = 1.f / (1.f + expf(-og));
            creg = fs * creg + is * tanhf(gg);
            float hv = os * tanhf(creg);
            int kidx = (slice << 2) + uq;
            d_Hbuf[(t + 1) & 1][dir][kidx][ub] = hv;
            d_Hout[dir][t][kidx][ub] = hv;
        }
        __threadfence();
        __syncthreads();
        target += 128u;
        if (tid == 0) {
            atomicAdd(&d_ctr, 1u);
            while (*((volatile unsigned*)&d_ctr) < target) {}
        }
        __syncthreads();
    }
}

// ------------------------- output assembly -------------------------
__global__ void outk(float* __restrict__ out, int out_size) {
    int idx = blockIdx.x * 256 + threadIdx.x;
    if (idx >= out_size) return;
    if (idx < 16777216) {
        int j = idx & 511;
        int t = (idx >> 9) & 1023;
        int sb = idx >> 19;
        int L = d_lens[sb];
        float v = 0.f;
        if (t < L) {
            if (j < 256) v = d_Hout[0][t][j][sb];
            else v = d_Hout[1][L - 1 - t][j - 256][sb];
        }
        out[idx] = v;
    } else {
        int k = idx - 16777216;
        if (k < 32) out[idx] = (float)d_order[k];
        else out[idx] = 0.f;
    }
}

// ------------------------- launch -------------------------
extern "C" void kernel_launch(void* const* d_in, const int* in_sizes, int n_in,
                              void* d_out, int out_size) {
    const float* x = (const float*)d_in[0];
    const int* xlen = (const int*)d_in[1];
    const float* W0 = (const float*)d_in[2];
    const float* b0 = (const float*)d_in[3];
    const float* W1 = (const float*)d_in[4];
    const float* b1 = (const float*)d_in[5];
    const float* W2 = (const float*)d_in[6];
    const float* b2 = (const float*)d_in[7];
    const float* Wih_f = (const float*)d_in[8];
    const float* Whh_f = (const float*)d_in[9];
    const float* bih_f = (const float*)d_in[10];
    const float* bhh_f = (const float*)d_in[11];
    const float* Wih_b = (const float*)d_in[12];
    const float* Whh_b = (const float*)d_in[13];
    const float* bih_b = (const float*)d_in[14];
    const float* bhh_b = (const float*)d_in[15];
    const float* h0 = (const float*)d_in[16];
    const float* c0 = (const float*)d_in[17];
    float* out = (float*)d_out;

    void *p_buf0, *p_buf1, *p_h;
    cudaGetSymbolAddress(&p_buf0, d_buf0);
    cudaGetSymbolAddress(&p_buf1, d_buf1);
    cudaGetSymbolAddress(&p_h, d_h);

    compute_order_k<<<1, 32>>>(xlen);

    gemm_relu_k<<<dim3(4, 256), 256>>>(x, W0, b0, (float*)p_buf0, 32768, 512, 80);
    gemm_relu_k<<<dim3(4, 256), 256>>>((const float*)p_buf0, W1, b1, (float*)p_buf1, 32768, 512, 512);
    gemm_relu_k<<<dim3(2, 256), 256>>>((const float*)p_buf1, W2, b2, (float*)p_h, 32768, 256, 512);

    deltas_k<<<8192, 256>>>();
    feat_k<<<8192, 256>>>();

    zgemm_k<<<dim3(8, 256, 2), 256>>>(Wih_f, Wih_b, bih_f, bhh_f, bih_b, bhh_b);

    cudaFuncSetAttribute(lstm_rec_k, cudaFuncAttributeMaxDynamicSharedMemorySize, 51776);
    lstm_rec_k<<<128, 256, 51776>>>(Whh_f, Whh_b, h0, c0);

    int total = out_size;
    outk<<<(total + 255) / 256, 256>>>(out, out_size);
}

// round 3
// speedup vs baseline: 1.2225x; 1.2225x over previous
#include <cuda_runtime.h>
#include <math.h>
#include <stdint.h>

// B=32, T=1024, D_IN=80, enc: 80->512->512->256 (ReLU), F=768, 4H=1024, H=256

// ------------------------- device scratch -------------------------
__device__ float d_buf0[32768 * 512];
__device__ float d_buf1[32768 * 512];
__device__ float d_h[32768 * 256];
__device__ float d_d1[32768 * 256];
__device__ float d_feat[32768 * 768];
__device__ float d_Z[32768 * 2048];        // [row=sb*1024+t][2048]: cols 0..1023 fwd, 1024..2047 bwd
__device__ float d_biascat[2048];
__device__ float d_Hbuf[2][2][256][32];
__device__ float d_Hout[2][1024][256][32];
__device__ int d_order[32];
__device__ int d_lens[32];
__device__ unsigned d_ctr;

// ------------------------- helpers -------------------------
__device__ __forceinline__ uint32_t s2u(const void* p) {
    uint32_t a;
    asm("{ .reg .u64 t; cvta.to.shared.u64 t, %1; cvt.u32.u64 %0, t; }" : "=r"(a) : "l"(p));
    return a;
}
__device__ __forceinline__ uint32_t cvt2bf(float lo, float hi) {
    uint32_t r;
    asm("cvt.rn.satfinite.bf16x2.f32 %0, %1, %2;" : "=r"(r) : "f"(hi), "f"(lo));
    return r;
}
__device__ __forceinline__ void ldsm4(uint32_t* r, uint32_t addr) {
    asm volatile("ldmatrix.sync.aligned.m8n8.x4.shared.b16 {%0,%1,%2,%3}, [%4];"
                 : "=r"(r[0]), "=r"(r[1]), "=r"(r[2]), "=r"(r[3]) : "r"(addr));
}
__device__ __forceinline__ void mma16816(float* c, const uint32_t* a, uint32_t b0, uint32_t b1) {
    asm volatile(
        "mma.sync.aligned.m16n8k16.row.col.f32.bf16.bf16.f32 "
        "{%0,%1,%2,%3}, {%4,%5,%6,%7}, {%8,%9}, {%0,%1,%2,%3};"
        : "+f"(c[0]), "+f"(c[1]), "+f"(c[2]), "+f"(c[3])
        : "r"(a[0]), "r"(a[1]), "r"(a[2]), "r"(a[3]), "r"(b0), "r"(b1));
}
// unit (row, c): 16B units, 4 per 64B row; swizzle keeps ldmatrix + stores conflict-free
#define SWZB(row, c) ((((uint32_t)(row)) << 6) + ((((uint32_t)(c) ^ (((uint32_t)(row) >> 1) & 3))) << 4))

__device__ __forceinline__ void st_unit(char* hi, char* lo, int row, int c, float4 v0, float4 v1) {
    float p0[4] = {v0.x, v0.z, v1.x, v1.z};
    float p1[4] = {v0.y, v0.w, v1.y, v1.w};
    uint32_t h[4], l[4];
#pragma unroll
    for (int j = 0; j < 4; ++j) {
        uint32_t ph = cvt2bf(p0[j], p1[j]);
        float hx = __uint_as_float(ph << 16);
        float hy = __uint_as_float(ph & 0xffff0000u);
        uint32_t pl = cvt2bf(p0[j] - hx, p1[j] - hy);
        h[j] = ph; l[j] = pl;
    }
    uint32_t off = SWZB(row, c);
    *(uint4*)(hi + off) = make_uint4(h[0], h[1], h[2], h[3]);
    *(uint4*)(lo + off) = make_uint4(l[0], l[1], l[2], l[3]);
}

// ------------------------- order (stable argsort desc) -------------------------
__global__ void compute_order_k(const int* __restrict__ xlen) {
    if (threadIdx.x == 0) {
        unsigned used = 0;
        for (int p = 0; p < 32; ++p) {
            int best = -1, bl = -2147483647;
            for (int j = 0; j < 32; ++j) {
                if (used & (1u << j)) continue;
                int L = xlen[j];
                if (L > bl) { bl = L; best = j; }
            }
            used |= (1u << best);
            d_order[p] = best;
            d_lens[p] = bl;
        }
        d_ctr = 0u;
    }
}

__global__ void bias_k(const float* __restrict__ bihf, const float* __restrict__ bhhf,
                       const float* __restrict__ bihb, const float* __restrict__ bhhb) {
    int j = blockIdx.x * 1024 + threadIdx.x;
    if (j < 1024) d_biascat[j] = bihf[j] + bhhf[j];
    else d_biascat[j] = bihb[j - 1024] + bhhb[j - 1024];
}

// ------------------------- fp32 GEMM (only for K=80 layer 0) -------------------------
__global__ void __launch_bounds__(256) gemm_relu_k(
    const float* __restrict__ A, const float* __restrict__ W,
    const float* __restrict__ bias, float* __restrict__ C,
    int M, int N, int K) {
    __shared__ float As[8][132];
    __shared__ float Ws[8][132];
    const int tid = threadIdx.x;
    const int n0 = blockIdx.x * 128, m0 = blockIdx.y * 128;
    const int lm = tid >> 1, lq = (tid & 1) * 4;
    const float* arow = A + (size_t)(m0 + lm) * K + lq;
    const float* wrow = W + (size_t)(n0 + lm) * K + lq;
    const int tx = tid & 15, ty = tid >> 4;
    float acc[8][8];
#pragma unroll
    for (int i = 0; i < 8; i++)
#pragma unroll
        for (int j = 0; j < 8; j++) acc[i][j] = 0.f;

    for (int k0 = 0; k0 < K; k0 += 8) {
        float4 av = *(const float4*)(arow + k0);
        float4 wv = *(const float4*)(wrow + k0);
        __syncthreads();
        As[lq + 0][lm] = av.x; As[lq + 1][lm] = av.y;
        As[lq + 2][lm] = av.z; As[lq + 3][lm] = av.w;
        Ws[lq + 0][lm] = wv.x; Ws[lq + 1][lm] = wv.y;
        Ws[lq + 2][lm] = wv.z; Ws[lq + 3][lm] = wv.w;
        __syncthreads();
#pragma unroll
        for (int k = 0; k < 8; k++) {
            float a[8], b[8];
            *(float4*)(a) = *(const float4*)&As[k][ty * 8];
            *(float4*)(a + 4) = *(const float4*)&As[k][ty * 8 + 4];
            *(float4*)(b) = *(const float4*)&Ws[k][tx * 8];
            *(float4*)(b + 4) = *(const float4*)&Ws[k][tx * 8 + 4];
#pragma unroll
            for (int i = 0; i < 8; i++)
#pragma unroll
                for (int j = 0; j < 8; j++) acc[i][j] += a[i] * b[j];
        }
    }
    float bs[8];
    *(float4*)bs = *(const float4*)&bias[n0 + tx * 8];
    *(float4*)(bs + 4) = *(const float4*)&bias[n0 + tx * 8 + 4];
#pragma unroll
    for (int i = 0; i < 8; i++) {
        float* crow = C + (size_t)(m0 + ty * 8 + i) * N + n0 + tx * 8;
        float4 v0, v1;
        v0.x = fmaxf(acc[i][0] + bs[0], 0.f);
        v0.y = fmaxf(acc[i][1] + bs[1], 0.f);
        v0.z = fmaxf(acc[i][2] + bs[2], 0.f);
        v0.w = fmaxf(acc[i][3] + bs[3], 0.f);
        v1.x = fmaxf(acc[i][4] + bs[4], 0.f);
        v1.y = fmaxf(acc[i][5] + bs[5], 0.f);
        v1.z = fmaxf(acc[i][6] + bs[6], 0.f);
        v1.w = fmaxf(acc[i][7] + bs[7], 0.f);
        *(float4*)crow = v0;
        *(float4*)(crow + 4) = v1;
    }
}

// ------------------------- HMMA split-bf16 GEMM -------------------------
// C[M][N] = (relu)(A[M][K] @ [Wa;Wb][N][K]^T + bias); 128x128 tile, BK=32,
// 3-term hi/lo split into shared fp32 accumulators. Double-buffered smem.
// smem: buf0 [Ah 8K | Al 8K | Bh 8K | Bl 8K] buf1 [...] bias 512B  -> 66048 B
template <int RELU>
__global__ void __launch_bounds__(256) gemm_mma_k(
    const float* __restrict__ A, const float* __restrict__ Wa,
    const float* __restrict__ Wb, int nsplit,
    const float* __restrict__ bias, float* __restrict__ C,
    int K, int ldo) {
    extern __shared__ char smc[];
    const int tid = threadIdx.x, lane = tid & 31, wid = tid >> 5;
    const int wm = wid >> 2, wn = wid & 3;
    const int n0 = blockIdx.x * 128, m0 = blockIdx.y * 128;
    const int NCH = K >> 5;
    const uint32_t sbase = s2u(smc);
    float* sBias = (float*)(smc + 65536);
    if (tid < 128) sBias[tid] = bias[n0 + tid];

    const int ra = tid >> 2, ca = tid & 3;
    const float* Ap0 = A + (size_t)(m0 + ra) * K + ca * 8;
    const float* Ap1 = A + (size_t)(m0 + 64 + ra) * K + ca * 8;
    const int ng0 = n0 + ra, ng1 = n0 + 64 + ra;
    const float* Bp0 = (ng0 < nsplit ? Wa + (size_t)ng0 * K : Wb + (size_t)(ng0 - nsplit) * K) + ca * 8;
    const float* Bp1 = (ng1 < nsplit ? Wa + (size_t)ng1 * K : Wb + (size_t)(ng1 - nsplit) * K) + ca * 8;

    float acc[4][4][4];
#pragma unroll
    for (int mi = 0; mi < 4; mi++)
#pragma unroll
        for (int j = 0; j < 4; j++)
#pragma unroll
            for (int q = 0; q < 4; q++) acc[mi][j][q] = 0.f;

    // stage chunk 0 into buf 0
    {
        char* base = smc;
        st_unit(base, base + 8192, ra, ca, *(const float4*)Ap0, *(const float4*)(Ap0 + 4));
        st_unit(base, base + 8192, 64 + ra, ca, *(const float4*)Ap1, *(const float4*)(Ap1 + 4));
        st_unit(base + 16384, base + 24576, ra, ca, *(const float4*)Bp0, *(const float4*)(Bp0 + 4));
        st_unit(base + 16384, base + 24576, 64 + ra, ca, *(const float4*)Bp1, *(const float4*)(Bp1 + 4));
    }
    __syncthreads();

    for (int i = 0; i < NCH; ++i) {
        float4 pa0, pa1, pa2, pa3, pb0, pb1, pb2, pb3;
        const bool more = (i + 1 < NCH);
        if (more) {
            const int kc = (i + 1) << 5;
            pa0 = *(const float4*)(Ap0 + kc); pa1 = *(const float4*)(Ap0 + kc + 4);
            pa2 = *(const float4*)(Ap1 + kc); pa3 = *(const float4*)(Ap1 + kc + 4);
            pb0 = *(const float4*)(Bp0 + kc); pb1 = *(const float4*)(Bp0 + kc + 4);
            pb2 = *(const float4*)(Bp1 + kc); pb3 = *(const float4*)(Bp1 + kc + 4);
        }
        const uint32_t ab = sbase + (i & 1) * 32768;
        const uint32_t bb = ab + 16384;
#pragma unroll
        for (int ks = 0; ks < 2; ++ks) {
            const int r = lane & 15;
            const int cu = (ks << 1) + (lane >> 4);
            uint32_t ah[4][4], al[4][4], bh[2][4], bl[2][4];
#pragma unroll
            for (int mi = 0; mi < 4; ++mi) {
                uint32_t off = SWZB(wm * 64 + mi * 16 + r, cu);
                ldsm4(ah[mi], ab + off);
                ldsm4(al[mi], ab + 8192 + off);
            }
#pragma unroll
            for (int ni = 0; ni < 2; ++ni) {
                uint32_t off = SWZB(wn * 32 + ni * 16 + r, cu);
                ldsm4(bh[ni], bb + off);
                ldsm4(bl[ni], bb + 8192 + off);
            }
#pragma unroll
            for (int mi = 0; mi < 4; ++mi)
#pragma unroll
                for (int j = 0; j < 4; ++j) {
                    const int ni = j >> 1, s = j & 1;
                    mma16816(acc[mi][j], ah[mi], bh[ni][s], bh[ni][s + 2]);
                    mma16816(acc[mi][j], al[mi], bh[ni][s], bh[ni][s + 2]);
                    mma16816(acc[mi][j], ah[mi], bl[ni][s], bl[ni][s + 2]);
                }
        }
        if (more) {
            char* base = smc + ((i + 1) & 1) * 32768;
            st_unit(base, base + 8192, ra, ca, pa0, pa1);
            st_unit(base, base + 8192, 64 + ra, ca, pa2, pa3);
            st_unit(base + 16384, base + 24576, ra, ca, pb0, pb1);
            st_unit(base + 16384, base + 24576, 64 + ra, ca, pb2, pb3);
        }
        __syncthreads();
    }

#pragma unroll
    for (int mi = 0; mi < 4; ++mi)
#pragma unroll
        for (int j = 0; j < 4; ++j) {
            const int row = m0 + wm * 64 + mi * 16 + (lane >> 2);
            const int colL = wn * 32 + j * 8 + (lane & 3) * 2;
            const float b0v = sBias[colL], b1v = sBias[colL + 1];
            float x0 = acc[mi][j][0] + b0v, x1 = acc[mi][j][1] + b1v;
            float x2 = acc[mi][j][2] + b0v, x3 = acc[mi][j][3] + b1v;
            if (RELU) {
                x0 = fmaxf(x0, 0.f); x1 = fmaxf(x1, 0.f);
                x2 = fmaxf(x2, 0.f); x3 = fmaxf(x3, 0.f);
            }
            *(float2*)(C + (size_t)row * ldo + n0 + colL) = make_float2(x0, x1);
            *(float2*)(C + (size_t)(row + 8) * ldo + n0 + colL) = make_float2(x2, x3);
        }
}

// ------------------------- deltas (WIN=2, edge replicate) -------------------------
__global__ void deltas_k() {
    int idx = blockIdx.x * 256 + threadIdx.x;
    if (idx >= 32 * 1024 * 64) return;
    int c4 = idx & 63, t = (idx >> 6) & 1023, b = idx >> 16;
    const float4* h4 = (const float4*)d_h;
    size_t base = (size_t)b * 65536;
    int tp1 = min(t + 1, 1023), tm1 = max(t - 1, 0);
    int tp2 = min(t + 2, 1023), tm2 = max(t - 2, 0);
    float4 a = h4[base + (size_t)tp1 * 64 + c4];
    float4 bb = h4[base + (size_t)tm1 * 64 + c4];
    float4 c = h4[base + (size_t)tp2 * 64 + c4];
    float4 d = h4[base + (size_t)tm2 * 64 + c4];
    float4 z;
    z.x = (a.x - bb.x) * 0.5f + (c.x - d.x) * 0.25f;
    z.y = (a.y - bb.y) * 0.5f + (c.y - d.y) * 0.25f;
    z.z = (a.z - bb.z) * 0.5f + (c.z - d.z) * 0.25f;
    z.w = (a.w - bb.w) * 0.5f + (c.w - d.w) * 0.25f;
    ((float4*)d_d1)[base + (size_t)t * 64 + c4] = z;
}

// ------------------------- feat assembly (sorted) -------------------------
__global__ void feat_k() {
    int idx = blockIdx.x * 256 + threadIdx.x;
    if (idx >= 32 * 1024 * 64) return;
    int c4 = idx & 63, t = (idx >> 6) & 1023, sb = idx >> 16;
    int b = d_order[sb];
    const float4* h4 = (const float4*)d_h;
    const float4* d14 = (const float4*)d_d1;
    float4* f4 = (float4*)d_feat;
    size_t base = (size_t)b * 65536;
    size_t srow = base + (size_t)t * 64 + c4;
    float4 hv = h4[srow];
    float4 d1v = d14[srow];
    int tp1 = min(t + 1, 1023), tm1 = max(t - 1, 0);
    int tp2 = min(t + 2, 1023), tm2 = max(t - 2, 0);
    float4 a = d14[base + (size_t)tp1 * 64 + c4];
    float4 bb = d14[base + (size_t)tm1 * 64 + c4];
    float4 c = d14[base + (size_t)tp2 * 64 + c4];
    float4 d = d14[base + (size_t)tm2 * 64 + c4];
    float4 d2v;
    d2v.x = (a.x - bb.x) * 0.5f + (c.x - d.x) * 0.25f;
    d2v.y = (a.y - bb.y) * 0.5f + (c.y - d.y) * 0.25f;
    d2v.z = (a.z - bb.z) * 0.5f + (c.z - d.z) * 0.25f;
    d2v.w = (a.w - bb.w) * 0.5f + (c.w - d.w) * 0.25f;
    size_t obase = ((size_t)sb * 1024 + t) * 192;
    f4[obase + c4] = hv;
    f4[obase + 64 + c4] = d1v;
    f4[obase + 128 + c4] = d2v;
}

// ------------------------- persistent bidirectional LSTM recurrence -------------------------
__global__ void __launch_bounds__(256, 1) lstm_rec_k(
    const float* __restrict__ Whh_f, const float* __restrict__ Whh_b,
    const float* __restrict__ h0, const float* __restrict__ c0) {
    extern __shared__ float sm[];
    float* sW = sm;                  // [r][k]: r*260+k
    float* sH = sm + 4160;           // [b][k]: b*260+k
    float* sG = sm + 4160 + 8320;    // [r][b]: r*33+b
    const int tid = threadIdx.x;
    const int cta = blockIdx.x;
    const int dir = cta >> 6;
    const int slice = cta & 63;
    const float* Whh = dir ? Whh_b : Whh_f;

    for (int i = tid; i < 4096; i += 256) {
        int rr = i >> 8, k = i & 255;
        int j = ((rr >> 2) << 8) + (slice << 2) + (rr & 3);
        sW[rr * 260 + k] = Whh[(size_t)j * 256 + k];
    }

    const int uq = tid >> 5, ub = tid & 31;
    float creg = 0.f;
    if (tid < 128) {
        int kidx = (slice << 2) + uq;
        creg = c0[(dir * 32 + ub) * 256 + kidx];
        d_Hbuf[0][dir][kidx][ub] = h0[(dir * 32 + ub) * 256 + kidx];
    }
    __syncthreads();
    unsigned target = 128u;
    if (tid == 0) {
        asm volatile("red.release.gpu.global.add.u32 [%0], %1;" :: "l"(&d_ctr), "r"(1u) : "memory");
        unsigned v;
        do {
            asm volatile("ld.acquire.gpu.global.u32 %0, [%1];" : "=r"(v) : "l"(&d_ctr) : "memory");
        } while (v < target);
    }
    __syncthreads();

    const int w = tid >> 5, lane = tid & 31;
    const int r = lane & 15, bh = lane >> 4;
    const int b0 = (w << 2) + bh, b1 = b0 + 2;
    const int jg = ((r >> 2) << 8) + (slice << 2) + (r & 3);
    const int L0r = d_lens[b0], L1r = d_lens[b1];
    const int zcol = dir * 1024 + jg;
    const float* Zb0 = d_Z + ((size_t)b0 << 10) * 2048 + zcol;
    const float* Zb1 = d_Z + ((size_t)b1 << 10) * 2048 + zcol;
    const float* sWr = sW + r * 260;

    for (int t = 0; t < 1024; ++t) {
        int tt0 = dir ? max(L0r - 1 - t, 0) : t;
        int tt1 = dir ? max(L1r - 1 - t, 0) : t;
        float acc0 = __ldg(Zb0 + (size_t)tt0 * 2048);
        float acc1 = __ldg(Zb1 + (size_t)tt1 * 2048);
        const float4* gh = (const float4*)&d_Hbuf[t & 1][dir][0][0];
#pragma unroll
        for (int it = 0; it < 8; ++it) {
            int i = tid + it * 256;
            float4 v = __ldcg(gh + i);
            int k = i >> 3, bq = (i & 7) << 2;
            sH[(bq + 0) * 260 + k] = v.x;
            sH[(bq + 1) * 260 + k] = v.y;
            sH[(bq + 2) * 260 + k] = v.z;
            sH[(bq + 3) * 260 + k] = v.w;
        }
        __syncthreads();
        const float* h0p = sH + b0 * 260;
        const float* h1p = sH + b1 * 260;
        float a0 = 0.f, a1 = 0.f, a2 = 0.f, a3 = 0.f;
        float e0 = 0.f, e1 = 0.f, e2 = 0.f, e3 = 0.f;
#pragma unroll 16
        for (int k = 0; k < 256; k += 4) {
            float4 wv = *(const float4*)(sWr + k);
            float4 hv0 = *(const float4*)(h0p + k);
            float4 hv1 = *(const float4*)(h1p + k);
            a0 += hv0.x * wv.x; a1 += hv0.y * wv.y; a2 += hv0.z * wv.z; a3 += hv0.w * wv.w;
            e0 += hv1.x * wv.x; e1 += hv1.y * wv.y; e2 += hv1.z * wv.z; e3 += hv1.w * wv.w;
        }
        acc0 += (a0 + a1) + (a2 + a3);
        acc1 += (e0 + e1) + (e2 + e3);
        sG[r * 33 + b0] = acc0;
        sG[r * 33 + b1] = acc1;
        __syncthreads();
        if (tid < 128) {
            float ig = sG[uq * 33 + ub];
            float fg = sG[(4 + uq) * 33 + ub];
            float gg = sG[(8 + uq) * 33 + ub];
            float og = sG[(12 + uq) * 33 + ub];
            float is = 1.f / (1.f + expf(-ig));
            float fs = 1.f / (1.f + expf(-fg));
            float os = 1.f / (1.f + expf(-og));
            creg = fs * creg + is * tanhf(gg);
            float hv = os * tanhf(creg);
            int kidx = (slice << 2) + uq;
            d_Hbuf[(t + 1) & 1][dir][kidx][ub] = hv;
            d_Hout[dir][t][kidx][ub] = hv;
        }
        __syncthreads();
        target += 128u;
        if (tid == 0) {
            asm volatile("red.release.gpu.global.add.u32 [%0], %1;" :: "l"(&d_ctr), "r"(1u) : "memory");
            unsigned v;
            do {
                asm volatile("ld.acquire.gpu.global.u32 %0, [%1];" : "=r"(v) : "l"(&d_ctr) : "memory");
            } while (v < target);
        }
        __syncthreads();
    }
}

// ------------------------- output assembly -------------------------
__global__ void outk(float* __restrict__ out, int out_size) {
    int idx = blockIdx.x * 256 + threadIdx.x;
    if (idx >= out_size) return;
    if (idx < 16777216) {
        int j = idx & 511;
        int t = (idx >> 9) & 1023;
        int sb = idx >> 19;
        int L = d_lens[sb];
        float v = 0.f;
        if (t < L) {
            if (j < 256) v = d_Hout[0][t][j][sb];
            else v = d_Hout[1][L - 1 - t][j - 256][sb];
        }
        out[idx] = v;
    } else {
        int k = idx - 16777216;
        if (k < 32) out[idx] = (float)d_order[k];
        else out[idx] = 0.f;
    }
}

// ------------------------- launch -------------------------
extern "C" void kernel_launch(void* const* d_in, const int* in_sizes, int n_in,
                              void* d_out, int out_size) {
    const float* x = (const float*)d_in[0];
    const int* xlen = (const int*)d_in[1];
    const float* W0 = (const float*)d_in[2];
    const float* b0 = (const float*)d_in[3];
    const float* W1 = (const float*)d_in[4];
    const float* b1 = (const float*)d_in[5];
    const float* W2 = (const float*)d_in[6];
    const float* b2 = (const float*)d_in[7];
    const float* Wih_f = (const float*)d_in[8];
    const float* Whh_f = (const float*)d_in[9];
    const float* bih_f = (const float*)d_in[10];
    const float* bhh_f = (const float*)d_in[11];
    const float* Wih_b = (const float*)d_in[12];
    const float* Whh_b = (const float*)d_in[13];
    const float* bih_b = (const float*)d_in[14];
    const float* bhh_b = (const float*)d_in[15];
    const float* h0 = (const float*)d_in[16];
    const float* c0 = (const float*)d_in[17];
    float* out = (float*)d_out;

    void *p_buf0, *p_buf1, *p_h, *p_feat, *p_Z, *p_bias;
    cudaGetSymbolAddress(&p_buf0, d_buf0);
    cudaGetSymbolAddress(&p_buf1, d_buf1);
    cudaGetSymbolAddress(&p_h, d_h);
    cudaGetSymbolAddress(&p_feat, d_feat);
    cudaGetSymbolAddress(&p_Z, d_Z);
    cudaGetSymbolAddress(&p_bias, d_biascat);

    static bool attr_done = false;
    if (!attr_done) {
        cudaFuncSetAttribute(gemm_mma_k<0>, cudaFuncAttributeMaxDynamicSharedMemorySize, 66048);
        cudaFuncSetAttribute(gemm_mma_k<1>, cudaFuncAttributeMaxDynamicSharedMemorySize, 66048);
        cudaFuncSetAttribute(lstm_rec_k, cudaFuncAttributeMaxDynamicSharedMemorySize, 52032);
        attr_done = true;
    }

    compute_order_k<<<1, 32>>>(xlen);
    bias_k<<<2, 1024>>>(bih_f, bhh_f, bih_b, bhh_b);

    // encoder
    gemm_relu_k<<<dim3(4, 256), 256>>>(x, W0, b0, (float*)p_buf0, 32768, 512, 80);
    gemm_mma_k<1><<<dim3(4, 256), 256, 66048>>>(
        (const float*)p_buf0, W1, W1, 0, b1, (float*)p_buf1, 512, 512);
    gemm_mma_k<1><<<dim3(2, 256), 256, 66048>>>(
        (const float*)p_buf1, W2, W2, 0, b2, (float*)p_h, 512, 256);

    deltas_k<<<8192, 256>>>();
    feat_k<<<8192, 256>>>();

    // Z = feat @ [Wih_f ; Wih_b]^T + biascat  (both directions fused)
    gemm_mma_k<0><<<dim3(16, 256), 256, 66048>>>(
        (const float*)p_feat, Wih_f, Wih_b, 1024, (const float*)p_bias, (float*)p_Z, 768, 2048);

    lstm_rec_k<<<128, 256, 52032>>>(Whh_f, Whh_b, h0, c0);

    outk<<<(out_size + 255) / 256, 256>>>(out, out_size);
}